// round 5
// baseline (speedup 1.0000x reference)
#include <cuda_runtime.h>
#include <math.h>
#include <stdint.h>

// Problem constants
#define B_     8
#define L_     8192
#define C_     512
#define H_     8
#define WS_    32
#define SHIFT_ 16
#define MLP_   2048
#define D_     64
#define NW_    256
#define NTOK   (B_*L_)          // 65536
#define NWIN   (B_*NW_)         // 2048

// GEMM tiling (tf32 mma.sync, K-interleaved [0,4,1,5,2,6,3,7] per 8-group)
#define BM 128
#define BN 128
#define BK 32
#define ASTR 40                  // smem row stride (floats): conflict-free LDS.64
#define NSTG 3
#define STAGE_F (BM*ASTR)        // 5120 floats per stage per matrix
#define SMEM_BYTES (2*NSTG*STAGE_F*4)   // 122880

// -------------------- scratch -------------------------------------------
__device__ float g_h  [(size_t)NTOK * C_];
__device__ float g_qkv[(size_t)NTOK * 3 * C_];
__device__ float g_o  [(size_t)NTOK * C_];
__device__ float g_y  [(size_t)NTOK * C_];
__device__ float g_mlp[(size_t)NTOK * MLP_];
__device__ float g_wr [3145728];
#define WR_QKV 0
#define WR_OUT 786432
#define WR_FC1 (786432 + 262144)
#define WR_FC2 (786432 + 262144 + 1048576)

// -------------------- helpers -------------------------------------------
__device__ __forceinline__ uint32_t smem_u32(const void* p) {
    uint32_t a;
    asm("{ .reg .u64 t; cvta.to.shared.u64 t, %1; cvt.u32.u64 %0, t; }" : "=r"(a) : "l"(p));
    return a;
}
__device__ __forceinline__ void cp_async16(uint32_t dst, const void* src) {
    asm volatile("cp.async.cg.shared.global [%0], [%1], 16;" :: "r"(dst), "l"(src));
}
__device__ __forceinline__ float tf32r(float x) {
    uint32_t u;
    asm("cvt.rna.tf32.f32 %0, %1;" : "=r"(u) : "f"(x));
    return __uint_as_float(u);
}
__device__ __forceinline__ void mma_tf32(float& d0, float& d1, float& d2, float& d3,
                                         uint32_t a0, uint32_t a1, uint32_t a2, uint32_t a3,
                                         uint32_t b0, uint32_t b1) {
    asm volatile(
        "mma.sync.aligned.m16n8k8.row.col.f32.tf32.tf32.f32 "
        "{%0,%1,%2,%3}, {%4,%5,%6,%7}, {%8,%9}, {%0,%1,%2,%3};"
        : "+f"(d0), "+f"(d1), "+f"(d2), "+f"(d3)
        : "r"(a0), "r"(a1), "r"(a2), "r"(a3), "r"(b0), "r"(b1));
}

// round to tf32 AND K-interleave each 8-group: stored = [l0,l4,l1,l5,l2,l6,l3,l7]
__global__ void round_perm_kernel(const float* __restrict__ in, float* __restrict__ out, int n8)
{
    int i = blockIdx.x * 256 + threadIdx.x;
    if (i < n8) {
        float4 a = ((const float4*)in)[2*i];
        float4 b = ((const float4*)in)[2*i+1];
        a.x = tf32r(a.x); a.y = tf32r(a.y); a.z = tf32r(a.z); a.w = tf32r(a.w);
        b.x = tf32r(b.x); b.y = tf32r(b.y); b.z = tf32r(b.z); b.w = tf32r(b.w);
        ((float4*)out)[2*i]   = make_float4(a.x, b.x, a.y, b.y);
        ((float4*)out)[2*i+1] = make_float4(a.z, b.z, a.w, b.w);
    }
}

// ==========================================================================
// tf32 tensor-core GEMM on K-interleaved operands.
//   EPI 0: +bias (plain output, NOT permuted)
//   EPI 1: GELU(acc+bias), output tf32-rounded + K-interleaved (feeds fc2)
//   EPI 2: acc + bias + res[row]      (final out, plain)
//   EPI 3: write row (l+SHIFT mod L): O[dst] = acc + bias + res[dst] (plain)
// ==========================================================================
template<int EPI>
__global__ __launch_bounds__(256)
void tc_gemm(const float* __restrict__ A, const float* __restrict__ W,
             const float* __restrict__ bias, const float* __restrict__ res,
             float* __restrict__ O, int K, int M)
{
    extern __shared__ float smem[];
    float* As = smem;                      // [NSTG][128][ASTR]
    float* Bs = smem + NSTG*STAGE_F;
    const uint32_t asb = smem_u32(As);
    const uint32_t bsb = smem_u32(Bs);

    const int tid  = threadIdx.x;
    const int wid  = tid >> 5;
    const int lane = tid & 31;
    const int wm   = wid >> 2;             // 0..1
    const int wn   = wid & 3;              // 0..3
    const int rowBase = blockIdx.y * BM;
    const int colBase = blockIdx.x * BN;

    const float* Ag = A + (size_t)rowBase * K;
    const float* Wg = W + (size_t)colBase * K;

    const int nIter = K >> 5;              // K/32 (>= 16 always here)

    auto issue_loads = [&](int it, int buf) {
        int k0 = it * BK;
        uint32_t aB = asb + buf * (STAGE_F*4);
        uint32_t bB = bsb + buf * (STAGE_F*4);
        #pragma unroll
        for (int t = 0; t < 4; t++) {
            int idx = tid + t * 256;       // 0..1023
            int row = idx >> 3;            // 0..127
            int c16 = idx & 7;             // 0..7
            uint32_t off = row * (ASTR*4) + c16 * 16;
            cp_async16(aB + off, Ag + (size_t)row * K + k0 + c16 * 4);
            cp_async16(bB + off, Wg + (size_t)row * K + k0 + c16 * 4);
        }
    };

    float acc[4][4][4];
    #pragma unroll
    for (int mi = 0; mi < 4; mi++)
        #pragma unroll
        for (int ni = 0; ni < 4; ni++)
            #pragma unroll
            for (int r = 0; r < 4; r++) acc[mi][ni][r] = 0.0f;

    issue_loads(0, 0);
    asm volatile("cp.async.commit_group;" ::: "memory");
    issue_loads(1, 1);
    asm volatile("cp.async.commit_group;" ::: "memory");

    const int lr = lane >> 2;              // 0..7
    const int lc = lane & 3;               // 0..3

    int buf = 0, nbuf = 2;
    for (int it = 0; it < nIter; it++) {
        if (it + 2 < nIter) issue_loads(it + 2, nbuf);
        asm volatile("cp.async.commit_group;" ::: "memory");
        asm volatile("cp.async.wait_group %0;" :: "n"(NSTG-1) : "memory");
        __syncthreads();

        const float* Ab = As + buf * STAGE_F;
        const float* Bb = Bs + buf * STAGE_F;

        #pragma unroll
        for (int kk = 0; kk < BK; kk += 8) {
            float2 av0[4], av1[4], bv[4];
            #pragma unroll
            for (int mi = 0; mi < 4; mi++) {
                int r0 = wm*64 + mi*16 + lr;
                av0[mi] = *((const float2*)(Ab + r0*ASTR + kk) + lc);
                av1[mi] = *((const float2*)(Ab + (r0+8)*ASTR + kk) + lc);
            }
            #pragma unroll
            for (int ni = 0; ni < 4; ni++) {
                int r0 = wn*32 + ni*8 + lr;
                bv[ni] = *((const float2*)(Bb + r0*ASTR + kk) + lc);
            }
            #pragma unroll
            for (int mi = 0; mi < 4; mi++)
                #pragma unroll
                for (int ni = 0; ni < 4; ni++)
                    mma_tf32(acc[mi][ni][0], acc[mi][ni][1], acc[mi][ni][2], acc[mi][ni][3],
                             __float_as_uint(av0[mi].x), __float_as_uint(av1[mi].x),
                             __float_as_uint(av0[mi].y), __float_as_uint(av1[mi].y),
                             __float_as_uint(bv[ni].x),  __float_as_uint(bv[ni].y));
        }
        __syncthreads();
        buf  = (buf  == NSTG-1) ? 0 : buf+1;
        nbuf = (nbuf == NSTG-1) ? 0 : nbuf+1;
    }

    // epilogue
    #pragma unroll
    for (int mi = 0; mi < 4; mi++) {
        int r0 = rowBase + wm*64 + mi*16 + lr;
        #pragma unroll
        for (int ni = 0; ni < 4; ni++) {
            int c0 = colBase + wn*32 + ni*8 + lc*2;
            float b0 = 0.f, b1 = 0.f;
            if (bias) { b0 = bias[c0]; b1 = bias[c0+1]; }
            #pragma unroll
            for (int half = 0; half < 2; half++) {
                int gr = r0 + half*8;
                float v0 = acc[mi][ni][half*2+0] + b0;
                float v1 = acc[mi][ni][half*2+1] + b1;
                if (EPI == 1) {
                    v0 = tf32r(0.5f * v0 * (1.0f + erff(v0 * 0.70710678118654752440f)));
                    v1 = tf32r(0.5f * v1 * (1.0f + erff(v1 * 0.70710678118654752440f)));
                    // permuted store: logical cols (2lc, 2lc+1) -> stored p0, p0+2
                    int p0 = ((lc & 1) << 2) | (lc >> 1);
                    float* ob = O + (size_t)gr * M + colBase + wn*32 + ni*8;
                    ob[p0]     = v0;
                    ob[p0 + 2] = v1;
                    continue;
                } else if (EPI == 2) {
                    const float2 rr = *(const float2*)(res + (size_t)gr * M + c0);
                    v0 += rr.x; v1 += rr.y;
                } else if (EPI == 3) {
                    int bb = gr >> 13;
                    int ll = gr & (L_ - 1);
                    gr = (bb << 13) | ((ll + SHIFT_) & (L_ - 1));
                    const float2 rr = *(const float2*)(res + (size_t)gr * M + c0);
                    v0 += rr.x; v1 += rr.y;
                }
                *(float2*)(O + (size_t)gr * M + c0) = make_float2(v0, v1);
            }
        }
    }
}

// ==========================================================================
// LayerNorm (+optional roll). Output tf32-rounded AND K-interleaved.
// Thread pair (2t, 2t+1) covers one 8-group via shfl exchange.
// ==========================================================================
__global__ void ln_roll_kernel(const float* __restrict__ in,
                               const float* __restrict__ gamma,
                               const float* __restrict__ beta,
                               float* __restrict__ out, int shift)
{
    int t   = blockIdx.x;
    int b   = t >> 13;
    int l   = t & (L_ - 1);
    int src = (b << 13) | ((l + shift) & (L_ - 1));
    int tid = threadIdx.x;

    float4 v = ((const float4*)(in + (size_t)src * C_))[tid];
    float s = v.x + v.y + v.z + v.w;
    float q = v.x*v.x + v.y*v.y + v.z*v.z + v.w*v.w;
    #pragma unroll
    for (int o = 16; o > 0; o >>= 1) {
        s += __shfl_xor_sync(0xffffffffu, s, o);
        q += __shfl_xor_sync(0xffffffffu, q, o);
    }
    __shared__ float ss[4], sq[4];
    int w = tid >> 5;
    if ((tid & 31) == 0) { ss[w] = s; sq[w] = q; }
    __syncthreads();
    s = ss[0] + ss[1] + ss[2] + ss[3];
    q = sq[0] + sq[1] + sq[2] + sq[3];

    float mean = s * (1.0f / C_);
    float var  = q * (1.0f / C_) - mean * mean;
    float inv  = rsqrtf(var + 1e-5f);

    float4 g4 = ((const float4*)gamma)[tid];
    float4 b4 = ((const float4*)beta)[tid];
    float4 r;
    r.x = tf32r((v.x - mean) * inv * g4.x + b4.x);
    r.y = tf32r((v.y - mean) * inv * g4.y + b4.y);
    r.z = tf32r((v.z - mean) * inv * g4.z + b4.z);
    r.w = tf32r((v.w - mean) * inv * g4.w + b4.w);

    // K-interleave with partner thread (tid^1)
    float4 p;
    p.x = __shfl_xor_sync(0xffffffffu, r.x, 1);
    p.y = __shfl_xor_sync(0xffffffffu, r.y, 1);
    p.z = __shfl_xor_sync(0xffffffffu, r.z, 1);
    p.w = __shfl_xor_sync(0xffffffffu, r.w, 1);
    float4 wv;
    if ((tid & 1) == 0) wv = make_float4(r.x, p.x, r.y, p.y);   // [l0,l4,l1,l5]
    else                wv = make_float4(p.z, r.z, p.w, r.w);   // [l2,l6,l3,l7]
    ((float4*)(out + (size_t)t * C_))[tid] = wv;
}

// ==========================================================================
// Windowed attention (double softmax). Output tf32-rounded + K-interleaved.
// ==========================================================================
__global__ __launch_bounds__(256)
void attn_kernel(const float* __restrict__ qkv, const float* __restrict__ relt,
                 float* __restrict__ out)
{
    int win = blockIdx.x;
    int h   = blockIdx.y;
    int wi  = win & (NW_ - 1);
    int tid = threadIdx.x;

    __shared__ float qs[WS_*D_], ks[WS_*D_], vs[WS_*D_];
    __shared__ float s[WS_][WS_+1];

    const float* base = qkv + (size_t)(win * WS_) * (3*C_) + h*D_;
    #pragma unroll
    for (int it = 0; it < 2; it++) {
        int i = tid + it*256;
        int r = i >> 4;
        int c = (i & 15) * 4;
        const float* rp = base + (size_t)r * (3*C_);
        *(float4*)&qs[r*D_+c] = *(const float4*)(rp + c);
        *(float4*)&ks[r*D_+c] = *(const float4*)(rp + C_  + c);
        *(float4*)&vs[r*D_+c] = *(const float4*)(rp + 2*C_ + c);
    }
    __syncthreads();

    {
        int x  = tid >> 3;
        int y0 = (tid & 7) * 4;
        float a0 = 0.f, a1 = 0.f, a2 = 0.f, a3 = 0.f;
        const float* qp = &qs[x*D_];
        #pragma unroll 8
        for (int kk = 0; kk < D_; kk++) {
            float qv = qp[kk];
            a0 = fmaf(qv, ks[(y0+0)*D_+kk], a0);
            a1 = fmaf(qv, ks[(y0+1)*D_+kk], a1);
            a2 = fmaf(qv, ks[(y0+2)*D_+kk], a2);
            a3 = fmaf(qv, ks[(y0+3)*D_+kk], a3);
        }
        const float scale = 0.125f;
        s[x][y0+0] = a0*scale; s[x][y0+1] = a1*scale;
        s[x][y0+2] = a2*scale; s[x][y0+3] = a3*scale;
    }
    __syncthreads();

    {
        int warp = tid >> 5, lane = tid & 31;
        bool lastw = (wi == NW_ - 1);
        #pragma unroll
        for (int rr = 0; rr < 4; rr++) {
            int r = warp*4 + rr;
            float v = s[r][lane];
            float mx = v;
            #pragma unroll
            for (int o = 16; o > 0; o >>= 1) mx = fmaxf(mx, __shfl_xor_sync(0xffffffffu, mx, o));
            float e = expf(v - mx);
            float sm = e;
            #pragma unroll
            for (int o = 16; o > 0; o >>= 1) sm += __shfl_xor_sync(0xffffffffu, sm, o);
            v = e / sm;
            float bm = relt[(r - lane + WS_ - 1) * H_ + h];
            if (lastw && ((r < SHIFT_) != (lane < SHIFT_))) bm -= 100.0f;
            v += bm;
            mx = v;
            #pragma unroll
            for (int o = 16; o > 0; o >>= 1) mx = fmaxf(mx, __shfl_xor_sync(0xffffffffu, mx, o));
            e = expf(v - mx);
            sm = e;
            #pragma unroll
            for (int o = 16; o > 0; o >>= 1) sm += __shfl_xor_sync(0xffffffffu, sm, o);
            s[r][lane] = e / sm;
        }
    }
    __syncthreads();

    {
        int x  = tid >> 3;
        int j0 = (tid & 7) * 8;
        float acc[8] = {0.f,0.f,0.f,0.f,0.f,0.f,0.f,0.f};
        #pragma unroll
        for (int y = 0; y < WS_; y++) {
            float sv = s[x][y];
            const float* vp = &vs[y*D_ + j0];
            #pragma unroll
            for (int jj = 0; jj < 8; jj++)
                acc[jj] = fmaf(sv, vp[jj], acc[jj]);
        }
        float* op = out + (size_t)(win*WS_ + x) * C_ + h*D_ + j0;
        // K-interleaved store: [a0,a4,a1,a5 | a2,a6,a3,a7]
        *(float4*)(op)   = make_float4(tf32r(acc[0]), tf32r(acc[4]), tf32r(acc[1]), tf32r(acc[5]));
        *(float4*)(op+4) = make_float4(tf32r(acc[2]), tf32r(acc[6]), tf32r(acc[3]), tf32r(acc[7]));
    }
}

// ==========================================================================
extern "C" void kernel_launch(void* const* d_in, const int* in_sizes, int n_in,
                              void* d_out, int out_size)
{
    const float* x      = (const float*)d_in[0];
    const float* w_qkv  = (const float*)d_in[1];
    const float* w_out  = (const float*)d_in[2];
    const float* b_out  = (const float*)d_in[3];
    const float* relt   = (const float*)d_in[4];
    const float* g1     = (const float*)d_in[5];
    const float* be1    = (const float*)d_in[6];
    const float* g2     = (const float*)d_in[7];
    const float* be2    = (const float*)d_in[8];
    const float* w_fc1  = (const float*)d_in[9];
    const float* b_fc1  = (const float*)d_in[10];
    const float* w_fc2  = (const float*)d_in[11];
    const float* b_fc2  = (const float*)d_in[12];
    float* out = (float*)d_out;

    float *hbuf, *qkvb, *obuf, *ybuf, *mlpb, *wr;
    cudaGetSymbolAddress((void**)&hbuf, g_h);
    cudaGetSymbolAddress((void**)&qkvb, g_qkv);
    cudaGetSymbolAddress((void**)&obuf, g_o);
    cudaGetSymbolAddress((void**)&ybuf, g_y);
    cudaGetSymbolAddress((void**)&mlpb, g_mlp);
    cudaGetSymbolAddress((void**)&wr,   g_wr);

    cudaFuncSetAttribute(tc_gemm<0>, cudaFuncAttributeMaxDynamicSharedMemorySize, SMEM_BYTES);
    cudaFuncSetAttribute(tc_gemm<1>, cudaFuncAttributeMaxDynamicSharedMemorySize, SMEM_BYTES);
    cudaFuncSetAttribute(tc_gemm<2>, cudaFuncAttributeMaxDynamicSharedMemorySize, SMEM_BYTES);
    cudaFuncSetAttribute(tc_gemm<3>, cudaFuncAttributeMaxDynamicSharedMemorySize, SMEM_BYTES);

    // 0) round+permute weights
    round_perm_kernel<<<(786432/8 + 255)/256, 256>>>(w_qkv, wr + WR_QKV, 786432/8);
    round_perm_kernel<<<(262144/8 + 255)/256, 256>>>(w_out, wr + WR_OUT, 262144/8);
    round_perm_kernel<<<(1048576/8 + 255)/256, 256>>>(w_fc1, wr + WR_FC1, 1048576/8);
    round_perm_kernel<<<(1048576/8 + 255)/256, 256>>>(w_fc2, wr + WR_FC2, 1048576/8);

    // 1) h = perm(tf32(roll(LN1(x), -SHIFT)))
    ln_roll_kernel<<<NTOK, 128>>>(x, g1, be1, hbuf, SHIFT_);

    // 2) qkv = h @ w_qkv^T  (plain output)
    tc_gemm<0><<<dim3(3*C_/BN, NTOK/BM), 256, SMEM_BYTES>>>(hbuf, wr + WR_QKV, nullptr, nullptr,
                                                            qkvb, C_, 3*C_);

    // 3) windowed attention -> perm(tf32) obuf
    attn_kernel<<<dim3(NWIN, H_), 256>>>(qkvb, relt, obuf);

    // 4+5) y = x + roll(obuf @ w_out^T + b_out, +SHIFT)
    tc_gemm<3><<<dim3(C_/BN, NTOK/BM), 256, SMEM_BYTES>>>(obuf, wr + WR_OUT, b_out, x,
                                                          ybuf, C_, C_);

    // 6) h2 = perm(tf32(LN2(y)))
    ln_roll_kernel<<<NTOK, 128>>>(ybuf, g2, be2, hbuf, 0);

    // 7) mlp = perm(tf32(gelu(h2 @ w_fc1^T + b_fc1)))
    tc_gemm<1><<<dim3(MLP_/BN, NTOK/BM), 256, SMEM_BYTES>>>(hbuf, wr + WR_FC1, b_fc1, nullptr,
                                                            mlpb, C_, MLP_);

    // 8) out = y + mlp @ w_fc2^T + b_fc2
    tc_gemm<2><<<dim3(C_/BN, NTOK/BM), 256, SMEM_BYTES>>>(mlpb, wr + WR_FC2, b_fc2, ybuf,
                                                          out, MLP_, C_);
}

// round 7
// speedup vs baseline: 1.4856x; 1.4856x over previous
#include <cuda_runtime.h>
#include <cuda_fp16.h>
#include <math.h>
#include <stdint.h>

// Problem constants
#define B_     8
#define L_     8192
#define C_     512
#define H_     8
#define WS_    32
#define SHIFT_ 16
#define MLP_   2048
#define D_     64
#define NW_    256
#define NTOK   (B_*L_)          // 65536
#define NWIN   (B_*NW_)         // 2048

// GEMM tiling (fp16 mma.sync m16n8k16 + ldmatrix)
#define BM 128
#define BN 128
#define BK 32                    // K halves per stage
#define HSTR 40                  // smem row stride in halves (80B) - ldmatrix conflict-free
#define STAGE_H (BM*HSTR)        // 5120 halves = 10240 B per stage per matrix
#define SMEM_BYTES (2*2*STAGE_H*2)   // A+B, 2 stages = 40960 B

// -------------------- scratch -------------------------------------------
__device__ __half g_h  [(size_t)NTOK * C_];        // LN out (half)
__device__ float  g_qkv[(size_t)NTOK * 3 * C_];    // qkv (fp32, feeds attention)
__device__ __half g_o  [(size_t)NTOK * C_];        // attention out (half)
__device__ float  g_y  [(size_t)NTOK * C_];        // residual stream (fp32)
__device__ __half g_mlp[(size_t)NTOK * MLP_];      // gelu out (half)
__device__ __half g_wh [3145728];                  // converted weights
#define WR_QKV 0
#define WR_OUT 786432
#define WR_FC1 (786432 + 262144)
#define WR_FC2 (786432 + 262144 + 1048576)

// -------------------- helpers -------------------------------------------
__device__ __forceinline__ uint32_t smem_u32(const void* p) {
    uint32_t a;
    asm("{ .reg .u64 t; cvta.to.shared.u64 t, %1; cvt.u32.u64 %0, t; }" : "=r"(a) : "l"(p));
    return a;
}
__device__ __forceinline__ void cp_async16(uint32_t dst, const void* src) {
    asm volatile("cp.async.cg.shared.global [%0], [%1], 16;" :: "r"(dst), "l"(src));
}
__device__ __forceinline__ void ldsm4(uint32_t* r, uint32_t addr) {
    asm volatile("ldmatrix.sync.aligned.m8n8.x4.shared.b16 {%0,%1,%2,%3}, [%4];"
                 : "=r"(r[0]), "=r"(r[1]), "=r"(r[2]), "=r"(r[3]) : "r"(addr));
}
__device__ __forceinline__ void mma_f16(float* d, const uint32_t* a, uint32_t b0, uint32_t b1) {
    asm volatile(
        "mma.sync.aligned.m16n8k16.row.col.f32.f16.f16.f32 "
        "{%0,%1,%2,%3},{%4,%5,%6,%7},{%8,%9},{%0,%1,%2,%3};"
        : "+f"(d[0]), "+f"(d[1]), "+f"(d[2]), "+f"(d[3])
        : "r"(a[0]), "r"(a[1]), "r"(a[2]), "r"(a[3]), "r"(b0), "r"(b1));
}

// fp32 -> fp16 weight conversion
__global__ void f2h_kernel(const float* __restrict__ in, __half* __restrict__ out, int n4)
{
    int i = blockIdx.x * 256 + threadIdx.x;
    if (i < n4) {
        float4 v = ((const float4*)in)[i];
        __half2 h0 = __floats2half2_rn(v.x, v.y);
        __half2 h1 = __floats2half2_rn(v.z, v.w);
        ((__half2*)out)[2*i]   = h0;
        ((__half2*)out)[2*i+1] = h1;
    }
}

// ==========================================================================
// fp16 tensor-core GEMM: O[N,M] = A[N,K] @ W[M,K]^T (+bias)(+epilogue)
//   EPI 0: +bias, fp32 out
//   EPI 1: GELU(acc+bias), HALF out (feeds fc2)
//   EPI 2: acc + bias + res[row], fp32 out (final)
//   EPI 3: write row (l+SHIFT mod L): O[dst] = acc + bias + res[dst], fp32
// 256 threads = 8 warps (2x4), warp tile 64x32, block 128x128, BK=32 halves.
// ==========================================================================
template<int EPI>
__global__ __launch_bounds__(256, 2)
void hgemm(const __half* __restrict__ A, const __half* __restrict__ W,
           const float* __restrict__ bias, const float* __restrict__ res,
           void* __restrict__ Ov, int K, int M)
{
    extern __shared__ __half smem[];
    __half* As = smem;                    // [2][128][HSTR]
    __half* Bs = smem + 2*STAGE_H;
    const uint32_t asb = smem_u32(As);
    const uint32_t bsb = smem_u32(Bs);

    const int tid  = threadIdx.x;
    const int wid  = tid >> 5;
    const int lane = tid & 31;
    const int wm   = wid >> 2;            // 0..1
    const int wn   = wid & 3;             // 0..3
    const int rowBase = blockIdx.y * BM;
    const int colBase = blockIdx.x * BN;

    const __half* Ag = A + (size_t)rowBase * K;
    const __half* Wg = W + (size_t)colBase * K;

    const int nIter = K >> 5;             // K/32

    // stage load: A and B each 512 x 16B chunks; thread does 2+2
    auto load_stage = [&](int it) {
        int buf = it & 1;
        int k0  = it * BK;
        uint32_t aB = asb + buf * (STAGE_H*2);
        uint32_t bB = bsb + buf * (STAGE_H*2);
        #pragma unroll
        for (int t = 0; t < 2; t++) {
            int idx = tid + t * 256;      // 0..511
            int row = idx >> 2;           // 0..127
            int c16 = idx & 3;            // 0..3
            uint32_t off = row * (HSTR*2) + c16 * 16;
            cp_async16(aB + off, Ag + (size_t)row * K + k0 + c16 * 8);
            cp_async16(bB + off, Wg + (size_t)row * K + k0 + c16 * 8);
        }
        asm volatile("cp.async.commit_group;" ::: "memory");
    };

    float acc[4][4][4];
    #pragma unroll
    for (int mi = 0; mi < 4; mi++)
        #pragma unroll
        for (int ni = 0; ni < 4; ni++)
            #pragma unroll
            for (int r = 0; r < 4; r++) acc[mi][ni][r] = 0.0f;

    load_stage(0);

    // ldmatrix lane geometry
    const int lr8  = lane & 7;            // row within 8
    const int lm01 = (lane >> 3) & 1;     // mat & 1
    const int lm2  = lane >> 4;           // mat >> 1
    // A: row = wm*64 + mi*16 + lm01*8 + lr8 ; col = kk + lm2*8
    // B: row = wn*32 + p*16  + lm2*8  + lr8 ; col = kk + lm01*8
    const uint32_t a_row = (uint32_t)(wm*64 + lm01*8 + lr8);
    const uint32_t b_row = (uint32_t)(wn*32 + lm2*8  + lr8);

    for (int it = 0; it < nIter; it++) {
        if (it + 1 < nIter) load_stage(it + 1);
        if (it + 1 < nIter)
            asm volatile("cp.async.wait_group 1;" ::: "memory");
        else
            asm volatile("cp.async.wait_group 0;" ::: "memory");
        __syncthreads();

        uint32_t aB = asb + (it & 1) * (STAGE_H*2);
        uint32_t bB = bsb + (it & 1) * (STAGE_H*2);

        #pragma unroll
        for (int kk = 0; kk < BK; kk += 16) {
            uint32_t af[4][4], bf[2][4];
            #pragma unroll
            for (int mi = 0; mi < 4; mi++)
                ldsm4(af[mi], aB + (uint32_t)(((a_row + mi*16) * HSTR + kk + lm2*8) * 2));
            #pragma unroll
            for (int p = 0; p < 2; p++)
                ldsm4(bf[p], bB + (uint32_t)(((b_row + p*16) * HSTR + kk + lm01*8) * 2));
            #pragma unroll
            for (int mi = 0; mi < 4; mi++)
                #pragma unroll
                for (int ni = 0; ni < 4; ni++)
                    mma_f16(acc[mi][ni], af[mi], bf[ni>>1][(ni&1)*2], bf[ni>>1][(ni&1)*2+1]);
        }
        __syncthreads();
    }

    // epilogue: lane i -> rows (i/4, i/4+8), cols (2*(i%4), +1)
    const int lr = lane >> 2;
    const int lc = lane & 3;
    float* Of = (float*)Ov;
    __half* Oh = (__half*)Ov;

    #pragma unroll
    for (int mi = 0; mi < 4; mi++) {
        int r0 = rowBase + wm*64 + mi*16 + lr;
        #pragma unroll
        for (int ni = 0; ni < 4; ni++) {
            int c0 = colBase + wn*32 + ni*8 + lc*2;
            float b0 = 0.f, b1 = 0.f;
            if (bias) { b0 = bias[c0]; b1 = bias[c0+1]; }
            #pragma unroll
            for (int half_ = 0; half_ < 2; half_++) {
                int gr = r0 + half_*8;
                float v0 = acc[mi][ni][half_*2+0] + b0;
                float v1 = acc[mi][ni][half_*2+1] + b1;
                if (EPI == 1) {
                    v0 = 0.5f * v0 * (1.0f + erff(v0 * 0.70710678118654752440f));
                    v1 = 0.5f * v1 * (1.0f + erff(v1 * 0.70710678118654752440f));
                    *(__half2*)(Oh + (size_t)gr * M + c0) = __floats2half2_rn(v0, v1);
                    continue;
                } else if (EPI == 2) {
                    const float2 rr = *(const float2*)(res + (size_t)gr * M + c0);
                    v0 += rr.x; v1 += rr.y;
                } else if (EPI == 3) {
                    int bb = gr >> 13;
                    int ll = gr & (L_ - 1);
                    gr = (bb << 13) | ((ll + SHIFT_) & (L_ - 1));
                    const float2 rr = *(const float2*)(res + (size_t)gr * M + c0);
                    v0 += rr.x; v1 += rr.y;
                }
                *(float2*)(Of + (size_t)gr * M + c0) = make_float2(v0, v1);
            }
        }
    }
}

// ==========================================================================
// LayerNorm (+optional source roll). fp32 in, HALF out.
// ==========================================================================
__global__ void ln_roll_kernel(const float* __restrict__ in,
                               const float* __restrict__ gamma,
                               const float* __restrict__ beta,
                               __half* __restrict__ out, int shift)
{
    int t   = blockIdx.x;
    int b   = t >> 13;
    int l   = t & (L_ - 1);
    int src = (b << 13) | ((l + shift) & (L_ - 1));
    int tid = threadIdx.x;

    float4 v = ((const float4*)(in + (size_t)src * C_))[tid];
    float s = v.x + v.y + v.z + v.w;
    float q = v.x*v.x + v.y*v.y + v.z*v.z + v.w*v.w;
    #pragma unroll
    for (int o = 16; o > 0; o >>= 1) {
        s += __shfl_xor_sync(0xffffffffu, s, o);
        q += __shfl_xor_sync(0xffffffffu, q, o);
    }
    __shared__ float ss[4], sq[4];
    int w = tid >> 5;
    if ((tid & 31) == 0) { ss[w] = s; sq[w] = q; }
    __syncthreads();
    s = ss[0] + ss[1] + ss[2] + ss[3];
    q = sq[0] + sq[1] + sq[2] + sq[3];

    float mean = s * (1.0f / C_);
    float var  = q * (1.0f / C_) - mean * mean;
    float inv  = rsqrtf(var + 1e-5f);

    float4 g4 = ((const float4*)gamma)[tid];
    float4 b4 = ((const float4*)beta)[tid];
    __half2 h0 = __floats2half2_rn((v.x - mean) * inv * g4.x + b4.x,
                                   (v.y - mean) * inv * g4.y + b4.y);
    __half2 h1 = __floats2half2_rn((v.z - mean) * inv * g4.z + b4.z,
                                   (v.w - mean) * inv * g4.w + b4.w);
    __half2* op = (__half2*)(out + (size_t)t * C_);
    op[2*tid]   = h0;
    op[2*tid+1] = h1;
}

// ==========================================================================
// Windowed attention (double softmax). fp32 in, HALF out.
// ==========================================================================
__global__ __launch_bounds__(256)
void attn_kernel(const float* __restrict__ qkv, const float* __restrict__ relt,
                 __half* __restrict__ out)
{
    int win = blockIdx.x;
    int h   = blockIdx.y;
    int wi  = win & (NW_ - 1);
    int tid = threadIdx.x;

    __shared__ float qs[WS_*D_], ks[WS_*D_], vs[WS_*D_];
    __shared__ float s[WS_][WS_+1];

    const float* base = qkv + (size_t)(win * WS_) * (3*C_) + h*D_;
    #pragma unroll
    for (int it = 0; it < 2; it++) {
        int i = tid + it*256;
        int r = i >> 4;
        int c = (i & 15) * 4;
        const float* rp = base + (size_t)r * (3*C_);
        *(float4*)&qs[r*D_+c] = *(const float4*)(rp + c);
        *(float4*)&ks[r*D_+c] = *(const float4*)(rp + C_  + c);
        *(float4*)&vs[r*D_+c] = *(const float4*)(rp + 2*C_ + c);
    }
    __syncthreads();

    {
        int x  = tid >> 3;
        int y0 = (tid & 7) * 4;
        float a0 = 0.f, a1 = 0.f, a2 = 0.f, a3 = 0.f;
        const float* qp = &qs[x*D_];
        #pragma unroll 8
        for (int kk = 0; kk < D_; kk++) {
            float qv = qp[kk];
            a0 = fmaf(qv, ks[(y0+0)*D_+kk], a0);
            a1 = fmaf(qv, ks[(y0+1)*D_+kk], a1);
            a2 = fmaf(qv, ks[(y0+2)*D_+kk], a2);
            a3 = fmaf(qv, ks[(y0+3)*D_+kk], a3);
        }
        const float scale = 0.125f;
        s[x][y0+0] = a0*scale; s[x][y0+1] = a1*scale;
        s[x][y0+2] = a2*scale; s[x][y0+3] = a3*scale;
    }
    __syncthreads();

    {
        int warp = tid >> 5, lane = tid & 31;
        bool lastw = (wi == NW_ - 1);
        #pragma unroll
        for (int rr = 0; rr < 4; rr++) {
            int r = warp*4 + rr;
            float v = s[r][lane];
            float mx = v;
            #pragma unroll
            for (int o = 16; o > 0; o >>= 1) mx = fmaxf(mx, __shfl_xor_sync(0xffffffffu, mx, o));
            float e = expf(v - mx);
            float sm = e;
            #pragma unroll
            for (int o = 16; o > 0; o >>= 1) sm += __shfl_xor_sync(0xffffffffu, sm, o);
            v = e / sm;
            float bm = relt[(r - lane + WS_ - 1) * H_ + h];
            if (lastw && ((r < SHIFT_) != (lane < SHIFT_))) bm -= 100.0f;
            v += bm;
            mx = v;
            #pragma unroll
            for (int o = 16; o > 0; o >>= 1) mx = fmaxf(mx, __shfl_xor_sync(0xffffffffu, mx, o));
            e = expf(v - mx);
            sm = e;
            #pragma unroll
            for (int o = 16; o > 0; o >>= 1) sm += __shfl_xor_sync(0xffffffffu, sm, o);
            s[r][lane] = e / sm;
        }
    }
    __syncthreads();

    {
        int x  = tid >> 3;
        int j0 = (tid & 7) * 8;
        float acc[8] = {0.f,0.f,0.f,0.f,0.f,0.f,0.f,0.f};
        #pragma unroll
        for (int y = 0; y < WS_; y++) {
            float sv = s[x][y];
            const float* vp = &vs[y*D_ + j0];
            #pragma unroll
            for (int jj = 0; jj < 8; jj++)
                acc[jj] = fmaf(sv, vp[jj], acc[jj]);
        }
        __half2* op = (__half2*)(out + (size_t)(win*WS_ + x) * C_ + h*D_ + j0);
        op[0] = __floats2half2_rn(acc[0], acc[1]);
        op[1] = __floats2half2_rn(acc[2], acc[3]);
        op[2] = __floats2half2_rn(acc[4], acc[5]);
        op[3] = __floats2half2_rn(acc[6], acc[7]);
    }
}

// ==========================================================================
extern "C" void kernel_launch(void* const* d_in, const int* in_sizes, int n_in,
                              void* d_out, int out_size)
{
    const float* x      = (const float*)d_in[0];
    const float* w_qkv  = (const float*)d_in[1];
    const float* w_out  = (const float*)d_in[2];
    const float* b_out  = (const float*)d_in[3];
    const float* relt   = (const float*)d_in[4];
    const float* g1     = (const float*)d_in[5];
    const float* be1    = (const float*)d_in[6];
    const float* g2     = (const float*)d_in[7];
    const float* be2    = (const float*)d_in[8];
    const float* w_fc1  = (const float*)d_in[9];
    const float* b_fc1  = (const float*)d_in[10];
    const float* w_fc2  = (const float*)d_in[11];
    const float* b_fc2  = (const float*)d_in[12];
    float* out = (float*)d_out;

    __half *hbuf, *obuf, *mlpb, *wh;
    float *qkvb, *ybuf;
    cudaGetSymbolAddress((void**)&hbuf, g_h);
    cudaGetSymbolAddress((void**)&qkvb, g_qkv);
    cudaGetSymbolAddress((void**)&obuf, g_o);
    cudaGetSymbolAddress((void**)&ybuf, g_y);
    cudaGetSymbolAddress((void**)&mlpb, g_mlp);
    cudaGetSymbolAddress((void**)&wh,   g_wh);

    cudaFuncSetAttribute(hgemm<0>, cudaFuncAttributeMaxDynamicSharedMemorySize, SMEM_BYTES);
    cudaFuncSetAttribute(hgemm<1>, cudaFuncAttributeMaxDynamicSharedMemorySize, SMEM_BYTES);
    cudaFuncSetAttribute(hgemm<2>, cudaFuncAttributeMaxDynamicSharedMemorySize, SMEM_BYTES);
    cudaFuncSetAttribute(hgemm<3>, cudaFuncAttributeMaxDynamicSharedMemorySize, SMEM_BYTES);

    // 0) convert weights to fp16
    f2h_kernel<<<(786432/4 + 255)/256, 256>>>(w_qkv, wh + WR_QKV, 786432/4);
    f2h_kernel<<<(262144/4 + 255)/256, 256>>>(w_out, wh + WR_OUT, 262144/4);
    f2h_kernel<<<(1048576/4 + 255)/256, 256>>>(w_fc1, wh + WR_FC1, 1048576/4);
    f2h_kernel<<<(1048576/4 + 255)/256, 256>>>(w_fc2, wh + WR_FC2, 1048576/4);

    // 1) h = half(roll(LN1(x), -SHIFT))
    ln_roll_kernel<<<NTOK, 128>>>(x, g1, be1, hbuf, SHIFT_);

    // 2) qkv = h @ w_qkv^T  (fp32 out)
    hgemm<0><<<dim3(3*C_/BN, NTOK/BM), 256, SMEM_BYTES>>>(hbuf, wh + WR_QKV, nullptr, nullptr,
                                                          qkvb, C_, 3*C_);

    // 3) windowed attention -> half obuf
    attn_kernel<<<dim3(NWIN, H_), 256>>>(qkvb, relt, obuf);

    // 4+5) y = x + roll(obuf @ w_out^T + b_out, +SHIFT)
    hgemm<3><<<dim3(C_/BN, NTOK/BM), 256, SMEM_BYTES>>>(obuf, wh + WR_OUT, b_out, x,
                                                        ybuf, C_, C_);

    // 6) h2 = half(LN2(y))
    ln_roll_kernel<<<NTOK, 128>>>(ybuf, g2, be2, hbuf, 0);

    // 7) mlp = half(gelu(h2 @ w_fc1^T + b_fc1))
    hgemm<1><<<dim3(MLP_/BN, NTOK/BM), 256, SMEM_BYTES>>>(hbuf, wh + WR_FC1, b_fc1, nullptr,
                                                          mlpb, C_, MLP_);

    // 8) out = y + mlp @ w_fc2^T + b_fc2
    hgemm<2><<<dim3(C_/BN, NTOK/BM), 256, SMEM_BYTES>>>(mlpb, wh + WR_FC2, b_fc2, ybuf,
                                                        out, MLP_, C_);
}